// round 1
// baseline (speedup 1.0000x reference)
#include <cuda_runtime.h>
#include <cstdint>

// Problem constants (fixed by the reference)
#define NROWS 20000
#define KNEI  32
#define CIN   512
#define COUT  512

// Scratch for the aggregated (mean) neighbor features: [NROWS, CIN] fp32 = 40 MB.
// __device__ global (no allocation in kernel_launch — allocation guards).
__device__ float g_agg[(size_t)NROWS * CIN];

// ---------------------------------------------------------------------------
// Kernel 1: agg[n][c] = mean_k neigh[n][k][c]
// One thread per (n, c4) float4. 32 independent float4 loads per thread (MLP=32),
// coalesced across c within a warp. Pure HBM-bound: 1.31 GB read + 40 MB write.
// ---------------------------------------------------------------------------
__global__ void mean_kernel(const float* __restrict__ neigh,
                            float* __restrict__ agg) {
    int idx = blockIdx.x * blockDim.x + threadIdx.x;  // n*(CIN/4) + c4
    if (idx >= NROWS * (CIN / 4)) return;
    int n  = idx >> 7;        // / (CIN/4) == /128
    int c4 = idx & 127;

    const float4* base = reinterpret_cast<const float4*>(neigh)
                       + (size_t)n * KNEI * (CIN / 4) + c4;
    float4 acc = make_float4(0.f, 0.f, 0.f, 0.f);
#pragma unroll
    for (int k = 0; k < KNEI; k++) {
        float4 v = base[(size_t)k * (CIN / 4)];
        acc.x += v.x; acc.y += v.y; acc.z += v.z; acc.w += v.w;
    }
    const float s = 1.0f / (float)KNEI;
    acc.x *= s; acc.y *= s; acc.z *= s; acc.w *= s;
    reinterpret_cast<float4*>(agg)[idx] = acc;
}

// ---------------------------------------------------------------------------
// Kernel 2: out[m][o] = sum_c x[m][c]*Wl[o][c] + sum_c agg[m][c]*Wr[o][c]
//                       + bl[o] + br[o]
// Classic register-tiled SGEMM: BM=128, BN=128, BK=8, 256 threads, 8x8 per
// thread. The K dimension is the 1024-wide virtual concat [x | agg] against
// [Wl ; Wr]: k-tiles 0..63 read (x, Wl), 64..127 read (agg, Wr).
// ---------------------------------------------------------------------------
#define BM 128
#define BN 128
#define BK 8
#define TM 8
#define TN 8

__global__ __launch_bounds__(256)
void sage_gemm_kernel(const float* __restrict__ x,
                      const float* __restrict__ agg,
                      const float* __restrict__ Wl,
                      const float* __restrict__ Wr,
                      const float* __restrict__ bl,
                      const float* __restrict__ br,
                      float* __restrict__ out) {
    __shared__ float As[BK][BM];  // As[k][m]
    __shared__ float Bs[BK][BN];  // Bs[k][n]

    const int tid = threadIdx.x;
    const int bm = blockIdx.y * BM;  // row (node) offset
    const int bn = blockIdx.x * BN;  // col (output-feature) offset

    const int tx = tid & 15;         // 16 thread-cols
    const int ty = tid >> 4;         // 16 thread-rows
    const int m0 = ty * TM;
    const int n0 = tx * TN;

    float acc[TM][TN];
#pragma unroll
    for (int i = 0; i < TM; i++)
#pragma unroll
        for (int j = 0; j < TN; j++) acc[i][j] = 0.f;

    // A loader: 128 rows x 8 k -> one float4 per thread.
    const int arow = tid >> 1;
    const int acol = (tid & 1) * 4;
    // B loader: 128 n-rows x 8 k -> one float4 per thread.
    const int brow = tid >> 1;
    const int bcol = (tid & 1) * 4;

    const int gm_a = bm + arow;      // global A row for this thread's load
    const bool a_ok = (gm_a < NROWS);

    for (int kt = 0; kt < (2 * CIN) / BK; kt++) {
        const bool first = (kt < CIN / BK);
        const float* A = first ? x : agg;
        const float* W = first ? Wl : Wr;
        const int kcol = (kt * BK) & (CIN - 1);  // k offset within the 512 block

        // ---- load A tile (guard M edge) ----
        float4 av = make_float4(0.f, 0.f, 0.f, 0.f);
        if (a_ok)
            av = *reinterpret_cast<const float4*>(A + (size_t)gm_a * CIN + kcol + acol);
        As[acol + 0][arow] = av.x;
        As[acol + 1][arow] = av.y;
        As[acol + 2][arow] = av.z;
        As[acol + 3][arow] = av.w;

        // ---- load B tile: W[bn+brow][kcol + bcol .. +3] (COUT=512, BN=128, always in range) ----
        float4 bv = *reinterpret_cast<const float4*>(W + (size_t)(bn + brow) * CIN + kcol + bcol);
        Bs[bcol + 0][brow] = bv.x;
        Bs[bcol + 1][brow] = bv.y;
        Bs[bcol + 2][brow] = bv.z;
        Bs[bcol + 3][brow] = bv.w;

        __syncthreads();

#pragma unroll
        for (int k = 0; k < BK; k++) {
            float ra[TM], rb[TN];
            // vector loads from shared
            float4 a0 = *reinterpret_cast<const float4*>(&As[k][m0]);
            float4 a1 = *reinterpret_cast<const float4*>(&As[k][m0 + 4]);
            float4 b0 = *reinterpret_cast<const float4*>(&Bs[k][n0]);
            float4 b1 = *reinterpret_cast<const float4*>(&Bs[k][n0 + 4]);
            ra[0] = a0.x; ra[1] = a0.y; ra[2] = a0.z; ra[3] = a0.w;
            ra[4] = a1.x; ra[5] = a1.y; ra[6] = a1.z; ra[7] = a1.w;
            rb[0] = b0.x; rb[1] = b0.y; rb[2] = b0.z; rb[3] = b0.w;
            rb[4] = b1.x; rb[5] = b1.y; rb[6] = b1.z; rb[7] = b1.w;
#pragma unroll
            for (int i = 0; i < TM; i++)
#pragma unroll
                for (int j = 0; j < TN; j++)
                    acc[i][j] += ra[i] * rb[j];
        }
        __syncthreads();
    }

    // ---- epilogue: add biases, store (guard M edge) ----
    float bias[TN];
#pragma unroll
    for (int j = 0; j < TN; j++)
        bias[j] = bl[bn + n0 + j] + br[bn + n0 + j];

#pragma unroll
    for (int i = 0; i < TM; i++) {
        int gm = bm + m0 + i;
        if (gm < NROWS) {
#pragma unroll
            for (int j = 0; j < TN; j += 4) {
                float4 v;
                v.x = acc[i][j + 0] + bias[j + 0];
                v.y = acc[i][j + 1] + bias[j + 1];
                v.z = acc[i][j + 2] + bias[j + 2];
                v.w = acc[i][j + 3] + bias[j + 3];
                *reinterpret_cast<float4*>(out + (size_t)gm * COUT + bn + n0 + j) = v;
            }
        }
    }
}

// ---------------------------------------------------------------------------
// Launch. Inputs (metadata order): x, neigh_x, W_l, b_l, W_r, b_r. Output fp32.
// ---------------------------------------------------------------------------
extern "C" void kernel_launch(void* const* d_in, const int* in_sizes, int n_in,
                              void* d_out, int out_size) {
    const float* x     = (const float*)d_in[0];
    const float* neigh = (const float*)d_in[1];
    const float* Wl    = (const float*)d_in[2];
    const float* bl    = (const float*)d_in[3];
    const float* Wr    = (const float*)d_in[4];
    const float* br    = (const float*)d_in[5];
    float* out = (float*)d_out;

    float* agg = nullptr;
    cudaGetSymbolAddress((void**)&agg, g_agg);

    // Kernel 1: mean aggregation
    {
        int total = NROWS * (CIN / 4);
        int threads = 256;
        int blocks = (total + threads - 1) / threads;
        mean_kernel<<<blocks, threads>>>(neigh, agg);
    }

    // Kernel 2: fused dual GEMM + bias
    {
        dim3 grid(COUT / BN, (NROWS + BM - 1) / BM);  // (4, 157)
        sage_gemm_kernel<<<grid, 256>>>(x, agg, Wl, Wr, bl, br, out);
    }
}

// round 3
// speedup vs baseline: 2.0583x; 2.0583x over previous
#include <cuda_runtime.h>
#include <cuda_bf16.h>
#include <cstdint>

// ---------------------------------------------------------------------------
// Problem constants
// ---------------------------------------------------------------------------
#define NROWS 20000
#define KNEI  32
#define CIN   512
#define COUT  512
#define KTOT  1024          // concat [x | mean(neigh)] along features

// GEMM tiling
#define BM 128
#define BN 128
#define BK 32               // 32 bf16 = 64 B per row
#define STAGES 3
#define STAGE_BYTES 16384   // (128*32 + 128*32) * 2B
#define NIT 96              // 3 combos * (1024/32)

// ---------------------------------------------------------------------------
// Scratch: split bf16 operands (no allocation allowed in kernel_launch).
// ---------------------------------------------------------------------------
__device__ __align__(16) __nv_bfloat16 g_A_hi[(size_t)NROWS * KTOT];
__device__ __align__(16) __nv_bfloat16 g_A_lo[(size_t)NROWS * KTOT];
__device__ __align__(16) __nv_bfloat16 g_B_hi[(size_t)COUT * KTOT];
__device__ __align__(16) __nv_bfloat16 g_B_lo[(size_t)COUT * KTOT];

// ---------------------------------------------------------------------------
// Helpers
// ---------------------------------------------------------------------------
__device__ __forceinline__ uint32_t smem_u32(const void* p) {
    uint32_t a;
    asm("{ .reg .u64 t; cvta.to.shared.u64 t, %1; cvt.u32.u64 %0, t; }"
        : "=r"(a) : "l"(p));
    return a;
}

// Swizzle for 64B rows: segment (16B) index ^= (row>>1)&3.
// off bits: [4:6)=seg, [6)=row bit0, [7:9)=row bits 1-2.
__device__ __forceinline__ uint32_t swz(uint32_t off) {
    return off ^ ((((off) >> 7) & 3u) << 4);
}

__device__ __forceinline__ void split_bf16(float v, __nv_bfloat16& hi, __nv_bfloat16& lo) {
    hi = __float2bfloat16_rn(v);
    lo = __float2bfloat16_rn(v - __bfloat162float(hi));
}

#define CP_ASYNC_16(dst, src, sz) \
    asm volatile("cp.async.ca.shared.global [%0], [%1], 16, %2;" \
                 :: "r"(dst), "l"(src), "r"(sz))
#define CP_ASYNC_COMMIT() asm volatile("cp.async.commit_group;" ::: "memory")
#define CP_ASYNC_WAIT1()  asm volatile("cp.async.wait_group 1;" ::: "memory")

__device__ __forceinline__ void ldmatrix_x4(uint32_t* r, uint32_t addr) {
    asm volatile("ldmatrix.sync.aligned.m8n8.x4.shared.b16 {%0,%1,%2,%3}, [%4];"
                 : "=r"(r[0]), "=r"(r[1]), "=r"(r[2]), "=r"(r[3]) : "r"(addr));
}
__device__ __forceinline__ void ldmatrix_x2(uint32_t* r, uint32_t addr) {
    asm volatile("ldmatrix.sync.aligned.m8n8.x2.shared.b16 {%0,%1}, [%2];"
                 : "=r"(r[0]), "=r"(r[1]) : "r"(addr));
}
__device__ __forceinline__ void mma_16816(float* c, const uint32_t* a, const uint32_t* b) {
    asm volatile(
        "mma.sync.aligned.m16n8k16.row.col.f32.bf16.bf16.f32 "
        "{%0,%1,%2,%3}, {%4,%5,%6,%7}, {%8,%9}, {%0,%1,%2,%3};"
        : "+f"(c[0]), "+f"(c[1]), "+f"(c[2]), "+f"(c[3])
        : "r"(a[0]), "r"(a[1]), "r"(a[2]), "r"(a[3]), "r"(b[0]), "r"(b[1]));
}

// ---------------------------------------------------------------------------
// Prep kernel 1: mean over neighbors -> split -> A[:, 512:1024]
// ---------------------------------------------------------------------------
__global__ void mean_split_kernel(const float* __restrict__ neigh) {
    int idx = blockIdx.x * blockDim.x + threadIdx.x;
    if (idx >= NROWS * (CIN / 4)) return;
    int n  = idx >> 7;
    int c4 = idx & 127;

    const float4* base = reinterpret_cast<const float4*>(neigh)
                       + (size_t)n * KNEI * (CIN / 4) + c4;
    float4 acc = make_float4(0.f, 0.f, 0.f, 0.f);
#pragma unroll
    for (int k = 0; k < KNEI; k++) {
        float4 v = base[(size_t)k * (CIN / 4)];
        acc.x += v.x; acc.y += v.y; acc.z += v.z; acc.w += v.w;
    }
    const float s = 1.0f / (float)KNEI;
    acc.x *= s; acc.y *= s; acc.z *= s; acc.w *= s;

    __nv_bfloat16 h[4], l[4];
    split_bf16(acc.x, h[0], l[0]);
    split_bf16(acc.y, h[1], l[1]);
    split_bf16(acc.z, h[2], l[2]);
    split_bf16(acc.w, h[3], l[3]);

    size_t off = (size_t)n * KTOT + CIN + c4 * 4;
    __nv_bfloat162* ph = reinterpret_cast<__nv_bfloat162*>(g_A_hi + off);
    __nv_bfloat162* pl = reinterpret_cast<__nv_bfloat162*>(g_A_lo + off);
    ph[0] = __halves2bfloat162(h[0], h[1]);
    ph[1] = __halves2bfloat162(h[2], h[3]);
    pl[0] = __halves2bfloat162(l[0], l[1]);
    pl[1] = __halves2bfloat162(l[2], l[3]);
}

// ---------------------------------------------------------------------------
// Prep kernel 2: split x -> A[:, 0:512]
// ---------------------------------------------------------------------------
__global__ void x_split_kernel(const float* __restrict__ x) {
    int idx = blockIdx.x * blockDim.x + threadIdx.x;
    if (idx >= NROWS * (CIN / 4)) return;
    int n  = idx >> 7;
    int c4 = idx & 127;

    float4 v = reinterpret_cast<const float4*>(x)[(size_t)n * (CIN / 4) + c4];
    __nv_bfloat16 h[4], l[4];
    split_bf16(v.x, h[0], l[0]);
    split_bf16(v.y, h[1], l[1]);
    split_bf16(v.z, h[2], l[2]);
    split_bf16(v.w, h[3], l[3]);

    size_t off = (size_t)n * KTOT + c4 * 4;
    __nv_bfloat162* ph = reinterpret_cast<__nv_bfloat162*>(g_A_hi + off);
    __nv_bfloat162* pl = reinterpret_cast<__nv_bfloat162*>(g_A_lo + off);
    ph[0] = __halves2bfloat162(h[0], h[1]);
    ph[1] = __halves2bfloat162(h[2], h[3]);
    pl[0] = __halves2bfloat162(l[0], l[1]);
    pl[1] = __halves2bfloat162(l[2], l[3]);
}

// ---------------------------------------------------------------------------
// Prep kernel 3: split weights -> B (Wl at cols 0:512, Wr at 512:1024)
// ---------------------------------------------------------------------------
__global__ void w_split_kernel(const float* __restrict__ Wl, const float* __restrict__ Wr) {
    int idx = blockIdx.x * blockDim.x + threadIdx.x;
    if (idx >= 2 * COUT * (CIN / 4)) return;
    int sel = idx >= COUT * (CIN / 4);
    int rem = idx - sel * COUT * (CIN / 4);
    int o  = rem >> 7;
    int c4 = rem & 127;

    const float* W = sel ? Wr : Wl;
    float4 v = reinterpret_cast<const float4*>(W)[(size_t)o * (CIN / 4) + c4];
    __nv_bfloat16 h[4], l[4];
    split_bf16(v.x, h[0], l[0]);
    split_bf16(v.y, h[1], l[1]);
    split_bf16(v.z, h[2], l[2]);
    split_bf16(v.w, h[3], l[3]);

    size_t off = (size_t)o * KTOT + sel * CIN + c4 * 4;
    __nv_bfloat162* ph = reinterpret_cast<__nv_bfloat162*>(g_B_hi + off);
    __nv_bfloat162* pl = reinterpret_cast<__nv_bfloat162*>(g_B_lo + off);
    ph[0] = __halves2bfloat162(h[0], h[1]);
    ph[1] = __halves2bfloat162(h[2], h[3]);
    pl[0] = __halves2bfloat162(l[0], l[1]);
    pl[1] = __halves2bfloat162(l[2], l[3]);
}

// ---------------------------------------------------------------------------
// GEMM: out[m][o] = sum_k A[m][k]*B[o][k] + bl[o] + br[o]
// D = Ahi*Bhi + Ahi*Blo + Alo*Bhi via mma.sync m16n8k16 bf16, fp32 accum.
// 256 threads, warp grid 2(m) x 4(n), warp tile 64x32, 3-stage cp.async.
// ---------------------------------------------------------------------------
__device__ __forceinline__ void load_stage(
    uint32_t sbase, int stage,
    const __nv_bfloat16* __restrict__ A, const __nv_bfloat16* __restrict__ B,
    int bm, int bn, int kcol, int tid)
{
    uint32_t abase = sbase + stage * STAGE_BYTES;
    uint32_t bbase = abase + 8192;
#pragma unroll
    for (int r = 0; r < 2; r++) {
        int s = r * 256 + tid;              // 0..511
        int row = s >> 2, seg = s & 3;
        int gm = bm + row;
        int ok = (gm < NROWS) ? 16 : 0;
        int gmc = (gm < NROWS) ? gm : (NROWS - 1);
        const void* src = A + (size_t)gmc * KTOT + kcol + seg * 8;
        CP_ASYNC_16(abase + swz((uint32_t)(row * 64 + seg * 16)), src, ok);
    }
#pragma unroll
    for (int r = 0; r < 2; r++) {
        int s = r * 256 + tid;
        int row = s >> 2, seg = s & 3;
        const void* src = B + (size_t)(bn + row) * KTOT + kcol + seg * 8;
        CP_ASYNC_16(bbase + swz((uint32_t)(row * 64 + seg * 16)), src, 16);
    }
}

__global__ __launch_bounds__(256)
void sage_mma_gemm(const __nv_bfloat16* __restrict__ Ahi,
                   const __nv_bfloat16* __restrict__ Alo,
                   const __nv_bfloat16* __restrict__ Bhi,
                   const __nv_bfloat16* __restrict__ Blo,
                   const float* __restrict__ bl,
                   const float* __restrict__ br,
                   float* __restrict__ out) {
    extern __shared__ __align__(128) char smem[];
    const uint32_t sbase = smem_u32(smem);
    const int tid  = threadIdx.x;
    const int wid  = tid >> 5;
    const int lane = tid & 31;
    const int warp_m = wid & 1;     // 0..1 -> 64-row slab
    const int warp_n = wid >> 1;    // 0..3 -> 32-col slab
    const int bm = blockIdx.y * BM;
    const int bn = blockIdx.x * BN;

    const __nv_bfloat16* Asel[3] = {Ahi, Ahi, Alo};
    const __nv_bfloat16* Bsel[3] = {Bhi, Blo, Bhi};

    float acc[4][4][4];
#pragma unroll
    for (int i = 0; i < 4; i++)
#pragma unroll
        for (int j = 0; j < 4; j++)
#pragma unroll
            for (int k = 0; k < 4; k++) acc[i][j][k] = 0.f;

    // Prologue: stages 0 and 1
    load_stage(sbase, 0, Asel[0], Bsel[0], bm, bn, 0, tid);
    CP_ASYNC_COMMIT();
    load_stage(sbase, 1, Asel[1], Bsel[1], bm, bn, 0, tid);
    CP_ASYNC_COMMIT();

    // Precomputed ldmatrix lane offsets (row, k8 within tile)
    const int a_msub = lane & 15;
    const int a_k8   = (lane >> 4) * 8;
    const int b_nsub = lane & 7;
    const int b_k8   = ((lane >> 3) & 1) * 8;

    for (int it = 0; it < NIT; it++) {
        CP_ASYNC_WAIT1();
        __syncthreads();

        // issue load for it+2 (buffer (it+2)%3 == (it-1)%3, done last iter)
        if (it + 2 < NIT) {
            int nit = it + 2;
            int combo = nit % 3;
            int kcol = (nit / 3) * BK;
            load_stage(sbase, nit % STAGES, Asel[combo], Bsel[combo], bm, bn, kcol, tid);
        }
        CP_ASYNC_COMMIT();

        // compute current stage
        uint32_t tbase = sbase + (it % STAGES) * STAGE_BYTES;
        uint32_t abase = tbase;
        uint32_t bbase = tbase + 8192;

#pragma unroll
        for (int kk = 0; kk < 2; kk++) {
            uint32_t afrag[4][4];
#pragma unroll
            for (int mi = 0; mi < 4; mi++) {
                uint32_t off = (uint32_t)((warp_m * 64 + mi * 16 + a_msub) * 64
                                          + (kk * 16 + a_k8) * 2);
                ldmatrix_x4(afrag[mi], abase + swz(off));
            }
            uint32_t bfrag[4][2];
#pragma unroll
            for (int ni = 0; ni < 4; ni++) {
                uint32_t off = (uint32_t)((warp_n * 32 + ni * 8 + b_nsub) * 64
                                          + (kk * 16 + b_k8) * 2);
                ldmatrix_x2(bfrag[ni], bbase + swz(off));
            }
#pragma unroll
            for (int mi = 0; mi < 4; mi++)
#pragma unroll
                for (int ni = 0; ni < 4; ni++)
                    mma_16816(acc[mi][ni], afrag[mi], bfrag[ni]);
        }
        __syncthreads();
    }

    // ---- epilogue: bias + store ----
    const int col0 = bn + warp_n * 32 + (lane & 3) * 2;
    float2 bias[4];
#pragma unroll
    for (int ni = 0; ni < 4; ni++) {
        int c = col0 + ni * 8;
        bias[ni].x = __ldg(bl + c)     + __ldg(br + c);
        bias[ni].y = __ldg(bl + c + 1) + __ldg(br + c + 1);
    }

    const int row0 = bm + warp_m * 64 + (lane >> 2);
#pragma unroll
    for (int mi = 0; mi < 4; mi++) {
#pragma unroll
        for (int h = 0; h < 2; h++) {
            int row = row0 + mi * 16 + h * 8;
            if (row < NROWS) {
                float* orow = out + (size_t)row * COUT;
#pragma unroll
                for (int ni = 0; ni < 4; ni++) {
                    float2 v;
                    v.x = acc[mi][ni][h * 2 + 0] + bias[ni].x;
                    v.y = acc[mi][ni][h * 2 + 1] + bias[ni].y;
                    *reinterpret_cast<float2*>(orow + col0 + ni * 8) = v;
                }
            }
        }
    }
}

// ---------------------------------------------------------------------------
// Launch. Inputs: x, neigh_x, W_l, b_l, W_r, b_r. Output fp32 [20000, 512].
// ---------------------------------------------------------------------------
extern "C" void kernel_launch(void* const* d_in, const int* in_sizes, int n_in,
                              void* d_out, int out_size) {
    const float* x     = (const float*)d_in[0];
    const float* neigh = (const float*)d_in[1];
    const float* Wl    = (const float*)d_in[2];
    const float* bl    = (const float*)d_in[3];
    const float* Wr    = (const float*)d_in[4];
    const float* br    = (const float*)d_in[5];
    float* out = (float*)d_out;

    __nv_bfloat16 *Ahi, *Alo, *Bhi, *Blo;
    cudaGetSymbolAddress((void**)&Ahi, g_A_hi);
    cudaGetSymbolAddress((void**)&Alo, g_A_lo);
    cudaGetSymbolAddress((void**)&Bhi, g_B_hi);
    cudaGetSymbolAddress((void**)&Blo, g_B_lo);

    // Prep: splits
    {
        int total = NROWS * (CIN / 4);
        x_split_kernel<<<(total + 255) / 256, 256>>>(x);
    }
    {
        int total = 2 * COUT * (CIN / 4);
        w_split_kernel<<<(total + 255) / 256, 256>>>(Wl, Wr);
    }
    {
        int total = NROWS * (CIN / 4);
        mean_split_kernel<<<(total + 255) / 256, 256>>>(neigh);
    }

    // GEMM (48KB dynamic smem — within the no-attribute limit)
    {
        dim3 grid(COUT / BN, (NROWS + BM - 1) / BM);  // (4, 157)
        sage_mma_gemm<<<grid, 256, STAGES * STAGE_BYTES>>>(Ahi, Alo, Bhi, Blo, bl, br, out);
    }
}

// round 4
// speedup vs baseline: 2.1251x; 1.0325x over previous
#include <cuda_runtime.h>
#include <cuda_bf16.h>
#include <cstdint>

// ---------------------------------------------------------------------------
// Problem constants
// ---------------------------------------------------------------------------
#define NROWS 20000
#define KNEI  32
#define CIN   512
#define COUT  512
#define KTOT  1024          // concat [x | mean(neigh)] along features

// GEMM tiling
#define BM 128
#define BN 128
#define BK 32               // 32 bf16 = 64 B per row
#define STAGES 3
#define STAGE_BYTES 16384   // (128*32 + 128*32) * 2B
#define NIT 96              // 3 combos * (1024/32)

// ---------------------------------------------------------------------------
// Scratch: split bf16 operands (no allocation allowed in kernel_launch).
// ---------------------------------------------------------------------------
__device__ __align__(16) __nv_bfloat16 g_A_hi[(size_t)NROWS * KTOT];
__device__ __align__(16) __nv_bfloat16 g_A_lo[(size_t)NROWS * KTOT];
__device__ __align__(16) __nv_bfloat16 g_B_hi[(size_t)COUT * KTOT];
__device__ __align__(16) __nv_bfloat16 g_B_lo[(size_t)COUT * KTOT];

// ---------------------------------------------------------------------------
// Helpers
// ---------------------------------------------------------------------------
__device__ __forceinline__ uint32_t smem_u32(const void* p) {
    uint32_t a;
    asm("{ .reg .u64 t; cvta.to.shared.u64 t, %1; cvt.u32.u64 %0, t; }"
        : "=r"(a) : "l"(p));
    return a;
}

// Swizzle for 64B rows: 16B-segment index ^= (row>>1)&3.
__device__ __forceinline__ uint32_t swz(uint32_t off) {
    return off ^ ((((off) >> 7) & 3u) << 4);
}

__device__ __forceinline__ void split_bf16(float v, __nv_bfloat16& hi, __nv_bfloat16& lo) {
    hi = __float2bfloat16_rn(v);
    lo = __float2bfloat16_rn(v - __bfloat162float(hi));
}

#define CP_ASYNC_16(dst, src, sz) \
    asm volatile("cp.async.ca.shared.global [%0], [%1], 16, %2;" \
                 :: "r"(dst), "l"(src), "r"(sz))
#define CP_ASYNC_COMMIT() asm volatile("cp.async.commit_group;" ::: "memory")
#define CP_ASYNC_WAIT1()  asm volatile("cp.async.wait_group 1;" ::: "memory")

__device__ __forceinline__ void ldmatrix_x4(uint32_t* r, uint32_t addr) {
    asm volatile("ldmatrix.sync.aligned.m8n8.x4.shared.b16 {%0,%1,%2,%3}, [%4];"
                 : "=r"(r[0]), "=r"(r[1]), "=r"(r[2]), "=r"(r[3]) : "r"(addr));
}
__device__ __forceinline__ void mma_16816(float* c, const uint32_t* a, const uint32_t* b) {
    asm volatile(
        "mma.sync.aligned.m16n8k16.row.col.f32.bf16.bf16.f32 "
        "{%0,%1,%2,%3}, {%4,%5,%6,%7}, {%8,%9}, {%0,%1,%2,%3};"
        : "+f"(c[0]), "+f"(c[1]), "+f"(c[2]), "+f"(c[3])
        : "r"(a[0]), "r"(a[1]), "r"(a[2]), "r"(a[3]), "r"(b[0]), "r"(b[1]));
}

// ---------------------------------------------------------------------------
// Prep kernel 1: mean over neighbors -> split -> A[:, 512:1024]
// ---------------------------------------------------------------------------
__global__ void mean_split_kernel(const float* __restrict__ neigh) {
    int idx = blockIdx.x * blockDim.x + threadIdx.x;
    if (idx >= NROWS * (CIN / 4)) return;
    int n  = idx >> 7;
    int c4 = idx & 127;

    const float4* base = reinterpret_cast<const float4*>(neigh)
                       + (size_t)n * KNEI * (CIN / 4) + c4;
    float4 acc = make_float4(0.f, 0.f, 0.f, 0.f);
#pragma unroll
    for (int k = 0; k < KNEI; k++) {
        float4 v = base[(size_t)k * (CIN / 4)];
        acc.x += v.x; acc.y += v.y; acc.z += v.z; acc.w += v.w;
    }
    const float s = 1.0f / (float)KNEI;
    acc.x *= s; acc.y *= s; acc.z *= s; acc.w *= s;

    __nv_bfloat16 h[4], l[4];
    split_bf16(acc.x, h[0], l[0]);
    split_bf16(acc.y, h[1], l[1]);
    split_bf16(acc.z, h[2], l[2]);
    split_bf16(acc.w, h[3], l[3]);

    size_t off = (size_t)n * KTOT + CIN + c4 * 4;
    __nv_bfloat162* ph = reinterpret_cast<__nv_bfloat162*>(g_A_hi + off);
    __nv_bfloat162* pl = reinterpret_cast<__nv_bfloat162*>(g_A_lo + off);
    ph[0] = __halves2bfloat162(h[0], h[1]);
    ph[1] = __halves2bfloat162(h[2], h[3]);
    pl[0] = __halves2bfloat162(l[0], l[1]);
    pl[1] = __halves2bfloat162(l[2], l[3]);
}

// ---------------------------------------------------------------------------
// Prep kernel 2: split x -> A[:, 0:512]
// ---------------------------------------------------------------------------
__global__ void x_split_kernel(const float* __restrict__ x) {
    int idx = blockIdx.x * blockDim.x + threadIdx.x;
    if (idx >= NROWS * (CIN / 4)) return;
    int n  = idx >> 7;
    int c4 = idx & 127;

    float4 v = reinterpret_cast<const float4*>(x)[(size_t)n * (CIN / 4) + c4];
    __nv_bfloat16 h[4], l[4];
    split_bf16(v.x, h[0], l[0]);
    split_bf16(v.y, h[1], l[1]);
    split_bf16(v.z, h[2], l[2]);
    split_bf16(v.w, h[3], l[3]);

    size_t off = (size_t)n * KTOT + c4 * 4;
    __nv_bfloat162* ph = reinterpret_cast<__nv_bfloat162*>(g_A_hi + off);
    __nv_bfloat162* pl = reinterpret_cast<__nv_bfloat162*>(g_A_lo + off);
    ph[0] = __halves2bfloat162(h[0], h[1]);
    ph[1] = __halves2bfloat162(h[2], h[3]);
    pl[0] = __halves2bfloat162(l[0], l[1]);
    pl[1] = __halves2bfloat162(l[2], l[3]);
}

// ---------------------------------------------------------------------------
// Prep kernel 3: split weights -> B (Wl at cols 0:512, Wr at 512:1024)
// ---------------------------------------------------------------------------
__global__ void w_split_kernel(const float* __restrict__ Wl, const float* __restrict__ Wr) {
    int idx = blockIdx.x * blockDim.x + threadIdx.x;
    if (idx >= 2 * COUT * (CIN / 4)) return;
    int sel = idx >= COUT * (CIN / 4);
    int rem = idx - sel * COUT * (CIN / 4);
    int o  = rem >> 7;
    int c4 = rem & 127;

    const float* W = sel ? Wr : Wl;
    float4 v = reinterpret_cast<const float4*>(W)[(size_t)o * (CIN / 4) + c4];
    __nv_bfloat16 h[4], l[4];
    split_bf16(v.x, h[0], l[0]);
    split_bf16(v.y, h[1], l[1]);
    split_bf16(v.z, h[2], l[2]);
    split_bf16(v.w, h[3], l[3]);

    size_t off = (size_t)o * KTOT + sel * CIN + c4 * 4;
    __nv_bfloat162* ph = reinterpret_cast<__nv_bfloat162*>(g_B_hi + off);
    __nv_bfloat162* pl = reinterpret_cast<__nv_bfloat162*>(g_B_lo + off);
    ph[0] = __halves2bfloat162(h[0], h[1]);
    ph[1] = __halves2bfloat162(h[2], h[3]);
    pl[0] = __halves2bfloat162(l[0], l[1]);
    pl[1] = __halves2bfloat162(l[2], l[3]);
}

// ---------------------------------------------------------------------------
// GEMM: out[m][o] = sum_k A[m][k]*B[o][k] + bl[o] + br[o]
// D = Ahi*Bhi + Ahi*Blo + Alo*Bhi via mma.sync m16n8k16 bf16, fp32 accum.
// 128 threads, warp grid 2(m) x 2(n), warp tile 64x64, 3-stage cp.async.
// ---------------------------------------------------------------------------
__device__ __forceinline__ void load_stage(
    uint32_t sbase, int stage,
    const __nv_bfloat16* __restrict__ A, const __nv_bfloat16* __restrict__ B,
    int bm, int bn, int kcol, int tid)
{
    uint32_t abase = sbase + stage * STAGE_BYTES;
    uint32_t bbase = abase + 8192;
#pragma unroll
    for (int r = 0; r < 4; r++) {
        int s = r * 128 + tid;              // 0..511
        int row = s >> 2, seg = s & 3;
        int gm = bm + row;
        int ok = (gm < NROWS) ? 16 : 0;
        int gmc = (gm < NROWS) ? gm : (NROWS - 1);
        const void* src = A + (size_t)gmc * KTOT + kcol + seg * 8;
        CP_ASYNC_16(abase + swz((uint32_t)(row * 64 + seg * 16)), src, ok);
    }
#pragma unroll
    for (int r = 0; r < 4; r++) {
        int s = r * 128 + tid;
        int row = s >> 2, seg = s & 3;
        const void* src = B + (size_t)(bn + row) * KTOT + kcol + seg * 8;
        CP_ASYNC_16(bbase + swz((uint32_t)(row * 64 + seg * 16)), src, 16);
    }
}

__global__ __launch_bounds__(128)
void sage_mma_gemm(const __nv_bfloat16* __restrict__ Ahi,
                   const __nv_bfloat16* __restrict__ Alo,
                   const __nv_bfloat16* __restrict__ Bhi,
                   const __nv_bfloat16* __restrict__ Blo,
                   const float* __restrict__ bl,
                   const float* __restrict__ br,
                   float* __restrict__ out) {
    extern __shared__ __align__(128) char smem[];
    const uint32_t sbase = smem_u32(smem);
    const int tid  = threadIdx.x;
    const int wid  = tid >> 5;
    const int lane = tid & 31;
    const int warp_m = wid & 1;     // 0..1 -> 64-row slab
    const int warp_n = wid >> 1;    // 0..1 -> 64-col slab
    const int bm = blockIdx.y * BM;
    const int bn = blockIdx.x * BN;

    const __nv_bfloat16* Asel[3] = {Ahi, Ahi, Alo};
    const __nv_bfloat16* Bsel[3] = {Bhi, Blo, Bhi};

    float acc[4][8][4];
#pragma unroll
    for (int i = 0; i < 4; i++)
#pragma unroll
        for (int j = 0; j < 8; j++)
#pragma unroll
            for (int k = 0; k < 4; k++) acc[i][j][k] = 0.f;

    // Prologue: stages 0 and 1
    load_stage(sbase, 0, Asel[0], Bsel[0], bm, bn, 0, tid);
    CP_ASYNC_COMMIT();
    load_stage(sbase, 1, Asel[1], Bsel[1], bm, bn, 0, tid);
    CP_ASYNC_COMMIT();

    // ldmatrix lane offsets:
    // A x4: m16 block -> row = msub (lane&15), k8 half = lane>>4
    const int a_msub = lane & 15;
    const int a_k8   = (lane >> 4) * 8;
    // B x4 over an n16 block: n = (lane&7) + ((lane>>4)&1)*8, k8 = ((lane>>3)&1)*8
    const int b_nsub = (lane & 7) + ((lane >> 4) & 1) * 8;
    const int b_k8   = ((lane >> 3) & 1) * 8;

    for (int it = 0; it < NIT; it++) {
        CP_ASYNC_WAIT1();
        __syncthreads();

        if (it + 2 < NIT) {
            int nit = it + 2;
            int combo = nit % 3;
            int kcol = (nit / 3) * BK;
            load_stage(sbase, nit % STAGES, Asel[combo], Bsel[combo], bm, bn, kcol, tid);
        }
        CP_ASYNC_COMMIT();

        uint32_t tbase = sbase + (it % STAGES) * STAGE_BYTES;
        uint32_t abase = tbase;
        uint32_t bbase = tbase + 8192;

#pragma unroll
        for (int kk = 0; kk < 2; kk++) {
            uint32_t afrag[4][4];
#pragma unroll
            for (int mi = 0; mi < 4; mi++) {
                uint32_t off = (uint32_t)((warp_m * 64 + mi * 16 + a_msub) * 64
                                          + (kk * 16 + a_k8) * 2);
                ldmatrix_x4(afrag[mi], abase + swz(off));
            }
            // B: 4 x4 loads, each covering an n16 x k16 block -> 8 n8 frags
            uint32_t bfrag[4][4];
#pragma unroll
            for (int nb = 0; nb < 4; nb++) {
                uint32_t off = (uint32_t)((warp_n * 64 + nb * 16 + b_nsub) * 64
                                          + (kk * 16 + b_k8) * 2);
                ldmatrix_x4(bfrag[nb], bbase + swz(off));
            }
#pragma unroll
            for (int mi = 0; mi < 4; mi++)
#pragma unroll
                for (int ni = 0; ni < 8; ni++)
                    mma_16816(acc[mi][ni], afrag[mi], &bfrag[ni >> 1][(ni & 1) * 2]);
        }
        __syncthreads();
    }

    // ---- epilogue: bias + store ----
    const int col0 = bn + warp_n * 64 + (lane & 3) * 2;
    float2 bias[8];
#pragma unroll
    for (int ni = 0; ni < 8; ni++) {
        int c = col0 + ni * 8;
        bias[ni].x = __ldg(bl + c)     + __ldg(br + c);
        bias[ni].y = __ldg(bl + c + 1) + __ldg(br + c + 1);
    }

    const int row0 = bm + warp_m * 64 + (lane >> 2);
#pragma unroll
    for (int mi = 0; mi < 4; mi++) {
#pragma unroll
        for (int h = 0; h < 2; h++) {
            int row = row0 + mi * 16 + h * 8;
            if (row < NROWS) {
                float* orow = out + (size_t)row * COUT;
#pragma unroll
                for (int ni = 0; ni < 8; ni++) {
                    float2 v;
                    v.x = acc[mi][ni][h * 2 + 0] + bias[ni].x;
                    v.y = acc[mi][ni][h * 2 + 1] + bias[ni].y;
                    *reinterpret_cast<float2*>(orow + col0 + ni * 8) = v;
                }
            }
        }
    }
}

// ---------------------------------------------------------------------------
// Launch. Inputs: x, neigh_x, W_l, b_l, W_r, b_r. Output fp32 [20000, 512].
// ---------------------------------------------------------------------------
extern "C" void kernel_launch(void* const* d_in, const int* in_sizes, int n_in,
                              void* d_out, int out_size) {
    const float* x     = (const float*)d_in[0];
    const float* neigh = (const float*)d_in[1];
    const float* Wl    = (const float*)d_in[2];
    const float* bl    = (const float*)d_in[3];
    const float* Wr    = (const float*)d_in[4];
    const float* br    = (const float*)d_in[5];
    float* out = (float*)d_out;

    __nv_bfloat16 *Ahi, *Alo, *Bhi, *Blo;
    cudaGetSymbolAddress((void**)&Ahi, g_A_hi);
    cudaGetSymbolAddress((void**)&Alo, g_A_lo);
    cudaGetSymbolAddress((void**)&Bhi, g_B_hi);
    cudaGetSymbolAddress((void**)&Blo, g_B_lo);

    // Prep: splits
    {
        int total = NROWS * (CIN / 4);
        x_split_kernel<<<(total + 255) / 256, 256>>>(x);
    }
    {
        int total = 2 * COUT * (CIN / 4);
        w_split_kernel<<<(total + 255) / 256, 256>>>(Wl, Wr);
    }
    {
        int total = NROWS * (CIN / 4);
        mean_split_kernel<<<(total + 255) / 256, 256>>>(neigh);
    }

    // GEMM (48KB dynamic smem, 128 threads, 2 CTAs/SM)
    {
        dim3 grid(COUT / BN, (NROWS + BM - 1) / BM);  // (4, 157)
        sage_mma_gemm<<<grid, 128, STAGES * STAGE_BYTES>>>(Ahi, Alo, Bhi, Blo, bl, br, out);
    }
}

// round 5
// speedup vs baseline: 2.2718x; 1.0690x over previous
#include <cuda_runtime.h>
#include <cuda_bf16.h>
#include <cstdint>

// ---------------------------------------------------------------------------
// Problem constants
// ---------------------------------------------------------------------------
#define NROWS 20000
#define KNEI  32
#define CIN   512
#define COUT  512
#define KTOT  1024          // concat [x | mean(neigh)] along features

// GEMM tiling
#define BM 128
#define BN 128
#define BK 32               // 32 bf16 = 64 B per row
#define STAGES 4
#define STAGE_BYTES 16384   // (128*32 + 128*32) * 2B
#define NIT 96              // 3 combos * (1024/32)

// ---------------------------------------------------------------------------
// Scratch: split bf16 operands (no allocation allowed in kernel_launch).
// ---------------------------------------------------------------------------
__device__ __align__(16) __nv_bfloat16 g_A_hi[(size_t)NROWS * KTOT];
__device__ __align__(16) __nv_bfloat16 g_A_lo[(size_t)NROWS * KTOT];
__device__ __align__(16) __nv_bfloat16 g_B_hi[(size_t)COUT * KTOT];
__device__ __align__(16) __nv_bfloat16 g_B_lo[(size_t)COUT * KTOT];

// ---------------------------------------------------------------------------
// Helpers
// ---------------------------------------------------------------------------
__device__ __forceinline__ uint32_t smem_u32(const void* p) {
    uint32_t a;
    asm("{ .reg .u64 t; cvta.to.shared.u64 t, %1; cvt.u32.u64 %0, t; }"
        : "=r"(a) : "l"(p));
    return a;
}

// Swizzle for 64B rows: 16B-segment index ^= (row>>1)&3.
__device__ __forceinline__ uint32_t swz(uint32_t off) {
    return off ^ ((((off) >> 7) & 3u) << 4);
}

__device__ __forceinline__ void split_bf16(float v, __nv_bfloat16& hi, __nv_bfloat16& lo) {
    hi = __float2bfloat16_rn(v);
    lo = __float2bfloat16_rn(v - __bfloat162float(hi));
}

#define CP_ASYNC_16(dst, src, sz) \
    asm volatile("cp.async.ca.shared.global [%0], [%1], 16, %2;" \
                 :: "r"(dst), "l"(src), "r"(sz))
#define CP_ASYNC_COMMIT() asm volatile("cp.async.commit_group;" ::: "memory")
#define CP_ASYNC_WAIT2()  asm volatile("cp.async.wait_group 2;" ::: "memory")

__device__ __forceinline__ void ldmatrix_x4(uint32_t* r, uint32_t addr) {
    asm volatile("ldmatrix.sync.aligned.m8n8.x4.shared.b16 {%0,%1,%2,%3}, [%4];"
                 : "=r"(r[0]), "=r"(r[1]), "=r"(r[2]), "=r"(r[3]) : "r"(addr));
}
__device__ __forceinline__ void mma_16816(float* c, const uint32_t* a, const uint32_t* b) {
    asm volatile(
        "mma.sync.aligned.m16n8k16.row.col.f32.bf16.bf16.f32 "
        "{%0,%1,%2,%3}, {%4,%5,%6,%7}, {%8,%9}, {%0,%1,%2,%3};"
        : "+f"(c[0]), "+f"(c[1]), "+f"(c[2]), "+f"(c[3])
        : "r"(a[0]), "r"(a[1]), "r"(a[2]), "r"(a[3]), "r"(b[0]), "r"(b[1]));
}

// ---------------------------------------------------------------------------
// Prep kernel 1: mean over neighbors -> split -> A[:, 512:1024]
// ---------------------------------------------------------------------------
__global__ void mean_split_kernel(const float* __restrict__ neigh) {
    int idx = blockIdx.x * blockDim.x + threadIdx.x;
    if (idx >= NROWS * (CIN / 4)) return;
    int n  = idx >> 7;
    int c4 = idx & 127;

    const float4* base = reinterpret_cast<const float4*>(neigh)
                       + (size_t)n * KNEI * (CIN / 4) + c4;
    float4 acc = make_float4(0.f, 0.f, 0.f, 0.f);
#pragma unroll
    for (int k = 0; k < KNEI; k++) {
        float4 v = base[(size_t)k * (CIN / 4)];
        acc.x += v.x; acc.y += v.y; acc.z += v.z; acc.w += v.w;
    }
    const float s = 1.0f / (float)KNEI;
    acc.x *= s; acc.y *= s; acc.z *= s; acc.w *= s;

    __nv_bfloat16 h[4], l[4];
    split_bf16(acc.x, h[0], l[0]);
    split_bf16(acc.y, h[1], l[1]);
    split_bf16(acc.z, h[2], l[2]);
    split_bf16(acc.w, h[3], l[3]);

    size_t off = (size_t)n * KTOT + CIN + c4 * 4;
    __nv_bfloat162* ph = reinterpret_cast<__nv_bfloat162*>(g_A_hi + off);
    __nv_bfloat162* pl = reinterpret_cast<__nv_bfloat162*>(g_A_lo + off);
    ph[0] = __halves2bfloat162(h[0], h[1]);
    ph[1] = __halves2bfloat162(h[2], h[3]);
    pl[0] = __halves2bfloat162(l[0], l[1]);
    pl[1] = __halves2bfloat162(l[2], l[3]);
}

// ---------------------------------------------------------------------------
// Prep kernel 2: split x -> A[:, 0:512]
// ---------------------------------------------------------------------------
__global__ void x_split_kernel(const float* __restrict__ x) {
    int idx = blockIdx.x * blockDim.x + threadIdx.x;
    if (idx >= NROWS * (CIN / 4)) return;
    int n  = idx >> 7;
    int c4 = idx & 127;

    float4 v = reinterpret_cast<const float4*>(x)[(size_t)n * (CIN / 4) + c4];
    __nv_bfloat16 h[4], l[4];
    split_bf16(v.x, h[0], l[0]);
    split_bf16(v.y, h[1], l[1]);
    split_bf16(v.z, h[2], l[2]);
    split_bf16(v.w, h[3], l[3]);

    size_t off = (size_t)n * KTOT + c4 * 4;
    __nv_bfloat162* ph = reinterpret_cast<__nv_bfloat162*>(g_A_hi + off);
    __nv_bfloat162* pl = reinterpret_cast<__nv_bfloat162*>(g_A_lo + off);
    ph[0] = __halves2bfloat162(h[0], h[1]);
    ph[1] = __halves2bfloat162(h[2], h[3]);
    pl[0] = __halves2bfloat162(l[0], l[1]);
    pl[1] = __halves2bfloat162(l[2], l[3]);
}

// ---------------------------------------------------------------------------
// Prep kernel 3: split weights -> B (Wl at cols 0:512, Wr at 512:1024)
// ---------------------------------------------------------------------------
__global__ void w_split_kernel(const float* __restrict__ Wl, const float* __restrict__ Wr) {
    int idx = blockIdx.x * blockDim.x + threadIdx.x;
    if (idx >= 2 * COUT * (CIN / 4)) return;
    int sel = idx >= COUT * (CIN / 4);
    int rem = idx - sel * COUT * (CIN / 4);
    int o  = rem >> 7;
    int c4 = rem & 127;

    const float* W = sel ? Wr : Wl;
    float4 v = reinterpret_cast<const float4*>(W)[(size_t)o * (CIN / 4) + c4];
    __nv_bfloat16 h[4], l[4];
    split_bf16(v.x, h[0], l[0]);
    split_bf16(v.y, h[1], l[1]);
    split_bf16(v.z, h[2], l[2]);
    split_bf16(v.w, h[3], l[3]);

    size_t off = (size_t)o * KTOT + sel * CIN + c4 * 4;
    __nv_bfloat162* ph = reinterpret_cast<__nv_bfloat162*>(g_B_hi + off);
    __nv_bfloat162* pl = reinterpret_cast<__nv_bfloat162*>(g_B_lo + off);
    ph[0] = __halves2bfloat162(h[0], h[1]);
    ph[1] = __halves2bfloat162(h[2], h[3]);
    pl[0] = __halves2bfloat162(l[0], l[1]);
    pl[1] = __halves2bfloat162(l[2], l[3]);
}

// ---------------------------------------------------------------------------
// GEMM: out[m][o] = sum_k A[m][k]*B[o][k] + bl[o] + br[o]
// D = Ahi*Bhi + Ahi*Blo + Alo*Bhi via mma.sync m16n8k16 bf16, fp32 accum.
// 128 threads, warp grid 2x2, warp tile 64x64, 4-stage cp.async pipeline,
// register double-buffered fragments, 1 __syncthreads per iteration.
// ---------------------------------------------------------------------------
__device__ __forceinline__ void load_stage(
    uint32_t sbase, int stage,
    const __nv_bfloat16* __restrict__ A, const __nv_bfloat16* __restrict__ B,
    int bm, int bn, int kcol, int tid)
{
    uint32_t abase = sbase + stage * STAGE_BYTES;
    uint32_t bbase = abase + 8192;
#pragma unroll
    for (int r = 0; r < 4; r++) {
        int s = r * 128 + tid;              // 0..511
        int row = s >> 2, seg = s & 3;
        int gm = bm + row;
        int ok = (gm < NROWS) ? 16 : 0;
        int gmc = (gm < NROWS) ? gm : (NROWS - 1);
        const void* src = A + (size_t)gmc * KTOT + kcol + seg * 8;
        CP_ASYNC_16(abase + swz((uint32_t)(row * 64 + seg * 16)), src, ok);
    }
#pragma unroll
    for (int r = 0; r < 4; r++) {
        int s = r * 128 + tid;
        int row = s >> 2, seg = s & 3;
        const void* src = B + (size_t)(bn + row) * KTOT + kcol + seg * 8;
        CP_ASYNC_16(bbase + swz((uint32_t)(row * 64 + seg * 16)), src, 16);
    }
}

__global__ __launch_bounds__(128)
void sage_mma_gemm(const __nv_bfloat16* __restrict__ Ahi,
                   const __nv_bfloat16* __restrict__ Alo,
                   const __nv_bfloat16* __restrict__ Bhi,
                   const __nv_bfloat16* __restrict__ Blo,
                   const float* __restrict__ bl,
                   const float* __restrict__ br,
                   float* __restrict__ out) {
    extern __shared__ __align__(128) char smem[];
    const uint32_t sbase = smem_u32(smem);
    const int tid  = threadIdx.x;
    const int wid  = tid >> 5;
    const int lane = tid & 31;
    const int warp_m = wid & 1;     // 0..1 -> 64-row slab
    const int warp_n = wid >> 1;    // 0..1 -> 64-col slab
    const int bm = blockIdx.y * BM;
    const int bn = blockIdx.x * BN;

    const __nv_bfloat16* Asel[3] = {Ahi, Ahi, Alo};
    const __nv_bfloat16* Bsel[3] = {Bhi, Blo, Bhi};

    float acc[4][8][4];
#pragma unroll
    for (int i = 0; i < 4; i++)
#pragma unroll
        for (int j = 0; j < 8; j++)
#pragma unroll
            for (int k = 0; k < 4; k++) acc[i][j][k] = 0.f;

    // ldmatrix lane offsets
    const int a_msub = lane & 15;
    const int a_k8   = (lane >> 4) * 8;
    const int b_nsub = (lane & 7) + ((lane >> 4) & 1) * 8;
    const int b_k8   = ((lane >> 3) & 1) * 8;

    // Per-warp precomputed swizzled intra-tile offsets (row-major byte offset
    // before swizzle; swz applied per use since base changes).
    uint32_t a_off[2][4], b_off[2][4];
#pragma unroll
    for (int kk = 0; kk < 2; kk++) {
#pragma unroll
        for (int mi = 0; mi < 4; mi++)
            a_off[kk][mi] = swz((uint32_t)((warp_m * 64 + mi * 16 + a_msub) * 64
                                           + (kk * 16 + a_k8) * 2));
#pragma unroll
        for (int nb = 0; nb < 4; nb++)
            b_off[kk][nb] = swz((uint32_t)((warp_n * 64 + nb * 16 + b_nsub) * 64
                                           + (kk * 16 + b_k8) * 2) + 8192);
    }

    // frag double buffers
    uint32_t afrag[2][4][4];
    uint32_t bfrag[2][4][4];

    // Prologue: fill stages 0..2 (iters 0,1,2)
    load_stage(sbase, 0, Asel[0], Bsel[0], bm, bn, 0, tid);
    CP_ASYNC_COMMIT();
    load_stage(sbase, 1, Asel[1], Bsel[1], bm, bn, 0, tid);
    CP_ASYNC_COMMIT();
    load_stage(sbase, 2, Asel[2], Bsel[2], bm, bn, 0, tid);
    CP_ASYNC_COMMIT();
    CP_ASYNC_WAIT2();            // stage 0 complete
    __syncthreads();

    // preload frags for it=0, kk=0
    {
        uint32_t tb = sbase;
#pragma unroll
        for (int mi = 0; mi < 4; mi++) ldmatrix_x4(afrag[0][mi], tb + a_off[0][mi]);
#pragma unroll
        for (int nb = 0; nb < 4; nb++) ldmatrix_x4(bfrag[0][nb], tb + b_off[0][nb]);
    }

    for (int it = 0; it < NIT; it++) {
        const uint32_t tb = sbase + (uint32_t)(it & 3) * STAGE_BYTES;

        // prefetch kk=1 frags (overlaps with kk=0 MMA burst below)
#pragma unroll
        for (int mi = 0; mi < 4; mi++) ldmatrix_x4(afrag[1][mi], tb + a_off[1][mi]);
#pragma unroll
        for (int nb = 0; nb < 4; nb++) ldmatrix_x4(bfrag[1][nb], tb + b_off[1][nb]);

        // MMA burst kk=0
#pragma unroll
        for (int mi = 0; mi < 4; mi++)
#pragma unroll
            for (int ni = 0; ni < 8; ni++)
                mma_16816(acc[mi][ni], afrag[0][mi], &bfrag[0][ni >> 1][(ni & 1) * 2]);

        // issue load for it+3 into stage (it+3)&3 == (it-1)&3 (readers done
        // since the barrier at the end of iter it-1)
        if (it + 3 < NIT) {
            int nit = it + 3;
            load_stage(sbase, nit & 3, Asel[nit % 3], Bsel[nit % 3],
                       bm, bn, (nit / 3) * BK, tid);
        }
        CP_ASYNC_COMMIT();

        // MMA burst kk=1
#pragma unroll
        for (int mi = 0; mi < 4; mi++)
#pragma unroll
            for (int ni = 0; ni < 8; ni++)
                mma_16816(acc[mi][ni], afrag[1][mi], &bfrag[1][ni >> 1][(ni & 1) * 2]);

        CP_ASYNC_WAIT2();        // stage (it+1)&3 load complete
        __syncthreads();         // all warps done reading stage it&3

        // preload next iteration's kk=0 frags
        if (it + 1 < NIT) {
            const uint32_t nb_ = sbase + (uint32_t)((it + 1) & 3) * STAGE_BYTES;
#pragma unroll
            for (int mi = 0; mi < 4; mi++) ldmatrix_x4(afrag[0][mi], nb_ + a_off[0][mi]);
#pragma unroll
            for (int nb = 0; nb < 4; nb++) ldmatrix_x4(bfrag[0][nb], nb_ + b_off[0][nb]);
        }
    }

    // ---- epilogue: bias + store ----
    const int col0 = bn + warp_n * 64 + (lane & 3) * 2;
    float2 bias[8];
#pragma unroll
    for (int ni = 0; ni < 8; ni++) {
        int c = col0 + ni * 8;
        bias[ni].x = __ldg(bl + c)     + __ldg(br + c);
        bias[ni].y = __ldg(bl + c + 1) + __ldg(br + c + 1);
    }

    const int row0 = bm + warp_m * 64 + (lane >> 2);
#pragma unroll
    for (int mi = 0; mi < 4; mi++) {
#pragma unroll
        for (int h = 0; h < 2; h++) {
            int row = row0 + mi * 16 + h * 8;
            if (row < NROWS) {
                float* orow = out + (size_t)row * COUT;
#pragma unroll
                for (int ni = 0; ni < 8; ni++) {
                    float2 v;
                    v.x = acc[mi][ni][h * 2 + 0] + bias[ni].x;
                    v.y = acc[mi][ni][h * 2 + 1] + bias[ni].y;
                    *reinterpret_cast<float2*>(orow + col0 + ni * 8) = v;
                }
            }
        }
    }
}

// ---------------------------------------------------------------------------
// Launch. Inputs: x, neigh_x, W_l, b_l, W_r, b_r. Output fp32 [20000, 512].
// ---------------------------------------------------------------------------
extern "C" void kernel_launch(void* const* d_in, const int* in_sizes, int n_in,
                              void* d_out, int out_size) {
    const float* x     = (const float*)d_in[0];
    const float* neigh = (const float*)d_in[1];
    const float* Wl    = (const float*)d_in[2];
    const float* bl    = (const float*)d_in[3];
    const float* Wr    = (const float*)d_in[4];
    const float* br    = (const float*)d_in[5];
    float* out = (float*)d_out;

    __nv_bfloat16 *Ahi, *Alo, *Bhi, *Blo;
    cudaGetSymbolAddress((void**)&Ahi, g_A_hi);
    cudaGetSymbolAddress((void**)&Alo, g_A_lo);
    cudaGetSymbolAddress((void**)&Bhi, g_B_hi);
    cudaGetSymbolAddress((void**)&Blo, g_B_lo);

    static bool attr_set = false;
    if (!attr_set) {
        cudaFuncSetAttribute(sage_mma_gemm,
                             cudaFuncAttributeMaxDynamicSharedMemorySize,
                             STAGES * STAGE_BYTES);
        attr_set = true;
    }

    // Prep: splits
    {
        int total = NROWS * (CIN / 4);
        x_split_kernel<<<(total + 255) / 256, 256>>>(x);
    }
    {
        int total = 2 * COUT * (CIN / 4);
        w_split_kernel<<<(total + 255) / 256, 256>>>(Wl, Wr);
    }
    {
        int total = NROWS * (CIN / 4);
        mean_split_kernel<<<(total + 255) / 256, 256>>>(neigh);
    }

    // GEMM (64KB dynamic smem, 128 threads, 2 CTAs/SM)
    {
        dim3 grid(COUT / BN, (NROWS + BM - 1) / BM);  // (4, 157)
        sage_mma_gemm<<<grid, 128, STAGES * STAGE_BYTES>>>(Ahi, Alo, Bhi, Blo, bl, br, out);
    }
}